// round 4
// baseline (speedup 1.0000x reference)
#include <cuda_runtime.h>
#include <cuda_bf16.h>
#include <cstdint>

// SupCon hard-contrastive loss via symmetric O*O^T (bf16 mma.sync):
//   nce = (1/2B) * sum_i [ log( exp(2 d_ip) + (2B-2)*B'_i/A'_i ) - 2 d_ip ]
// A'_i, B'_i = full-row sums of exp(d_ij), exp(3 d_ij) minus analytic
// self/partner terms. Triangular block tiles only; each CTA owns one
// 128-row A block (resident in smem) and up to 4 column tiles (B streamed),
// cutting L2 traffic ~40% vs tile-per-CTA. Off-diagonal tiles contribute
// row sums AND (symmetry) column sums via a bf16 smem transpose.

#define NROWS 8192
#define HALFN 4096
#define DDIM  512
#define TILE  128
#define KCH   64                  // bf16 per K-chunk
#define NCH   (DDIM / KCH)        // 8
#define PITCH 144                 // bytes/row in smem slab (128 data + 16 pad)
#define SLAB  (TILE * PITCH)      // 18432 B
#define NGROUPS 544               // sum_{bi<64} ceil((64-bi)/4)

// dynamic smem layout
#define SM_A  0                   // 8 slabs = 147456
#define SM_B  (8 * SLAB)          // 2 slabs = 36864
#define SM_T  (SM_B + 2 * SLAB)   // bf16 128x128 staging = 32768
#define SM_SZ (SM_T + 32768)      // 217088 bytes

__device__ __nv_bfloat16 g_O[(size_t)NROWS * DDIM];  // normalized rows, bf16
__device__ float g_sumE[NROWS];                      // sum_j exp(d_ij)
__device__ float g_sumE3[NROWS];                     // sum_j exp(3 d_ij)

// ---------------------------------------------------------------- helpers
__device__ __forceinline__ void cpasync16(uint32_t saddr, const void* gaddr) {
    asm volatile("cp.async.cg.shared.global [%0], [%1], 16;\n" ::
                 "r"(saddr), "l"(gaddr));
}
__device__ __forceinline__ void cp_commit() {
    asm volatile("cp.async.commit_group;\n");
}
__device__ __forceinline__ void cp_wait0() {
    asm volatile("cp.async.wait_group 0;\n" ::: "memory");
}
__device__ __forceinline__ void cp_wait1() {
    asm volatile("cp.async.wait_group 1;\n" ::: "memory");
}
__device__ __forceinline__ void cp_wait2() {
    asm volatile("cp.async.wait_group 2;\n" ::: "memory");
}
__device__ __forceinline__ void ldm_x4(uint32_t& r0, uint32_t& r1, uint32_t& r2,
                                       uint32_t& r3, uint32_t addr) {
    asm volatile("ldmatrix.sync.aligned.m8n8.x4.shared.b16 {%0,%1,%2,%3}, [%4];\n"
                 : "=r"(r0), "=r"(r1), "=r"(r2), "=r"(r3) : "r"(addr));
}
__device__ __forceinline__ void mma16816(float* d, const uint32_t* a,
                                         uint32_t b0, uint32_t b1) {
    asm volatile(
        "mma.sync.aligned.m16n8k16.row.col.f32.bf16.bf16.f32 "
        "{%0,%1,%2,%3}, {%4,%5,%6,%7}, {%8,%9}, {%0,%1,%2,%3};\n"
        : "+f"(d[0]), "+f"(d[1]), "+f"(d[2]), "+f"(d[3])
        : "r"(a[0]), "r"(a[1]), "r"(a[2]), "r"(a[3]), "r"(b0), "r"(b1));
}

// ------------------------------------------------- kernel 1: normalize -> bf16
__global__ __launch_bounds__(128) void normalize_kernel(const float* __restrict__ o1,
                                                        const float* __restrict__ o2) {
    const int row = blockIdx.x;
    const int tid = threadIdx.x;
    const float* src = (row < HALFN) ? (o1 + (size_t)row * DDIM)
                                     : (o2 + (size_t)(row - HALFN) * DDIM);
    float4 v = reinterpret_cast<const float4*>(src)[tid];
    float ss = v.x * v.x + v.y * v.y + v.z * v.z + v.w * v.w;
#pragma unroll
    for (int o = 16; o; o >>= 1) ss += __shfl_xor_sync(0xffffffffu, ss, o);
    __shared__ float ws[4];
    if ((tid & 31) == 0) ws[tid >> 5] = ss;
    __syncthreads();
    float rn = rsqrtf(ws[0] + ws[1] + ws[2] + ws[3]);
    __nv_bfloat162* dst =
        reinterpret_cast<__nv_bfloat162*>(g_O + (size_t)row * DDIM) + tid * 2;
    dst[0] = __floats2bfloat162_rn(v.x * rn, v.y * rn);
    dst[1] = __floats2bfloat162_rn(v.z * rn, v.w * rn);
    if (tid == 0) { g_sumE[row] = 0.f; g_sumE3[row] = 0.f; }
}

// ---------- kernel 2: A-resident group of up to 4 triangular tiles + epilogue
__global__ __launch_bounds__(256) void gemm_exp_sym() {
    extern __shared__ char smem[];
    const uint32_t sbase = (uint32_t)__cvta_generic_to_shared(smem);
    __nv_bfloat16* sTb = reinterpret_cast<__nv_bfloat16*>(smem + SM_T);
    const int tid  = threadIdx.x;
    const int lane = tid & 31;
    const int warp = tid >> 5;                  // 8 warps: 4 (M) x 2 (N)

    // decode group: bi (A row-block), bj0 = bi + 4*rem, nt tiles
    int rem = blockIdx.x;
    int bi = 0;
    for (; bi < 64; ++bi) { int g = (67 - bi) >> 2; if (rem < g) break; rem -= g; }
    const int bj0 = bi + rem * 4;
    const int nt = min(4, 64 - bj0);
    const int rowBase = bi * TILE;

    const int m_off = (warp >> 1) * 32;
    const int n_off = (warp & 1) * 64;

    // ldmatrix per-lane offsets (bytes within a slab)
    const int rA   = ((lane >> 3) & 1) * 8 + (lane & 7);
    const int segA = lane >> 4;
    int aoff[2];
#pragma unroll
    for (int mt = 0; mt < 2; ++mt)
        aoff[mt] = (m_off + mt * 16 + rA) * PITCH + segA * 16;

    const int rB   = (lane & 7) + ((lane >> 4) << 3);
    const int segB = (lane >> 3) & 1;
    int boff[4];
#pragma unroll
    for (int nq = 0; nq < 4; ++nq)
        boff[nq] = (n_off + nq * 16 + rB) * PITCH + segB * 16;

    // loaders: per chunk 128 rows x 8 segs of 16B = 1024 segs / 256 thr = 4 ea
    auto loadA = [&](int kc) {
#pragma unroll
        for (int j = 0; j < 4; ++j) {
            int seg = tid + j * 256;
            int r = seg >> 3, s8 = seg & 7;
            cpasync16(sbase + SM_A + kc * SLAB + r * PITCH + s8 * 16,
                      g_O + (size_t)(rowBase + r) * DDIM + kc * KCH + s8 * 8);
        }
    };
    auto loadB = [&](int bj, int kc, int buf) {
#pragma unroll
        for (int j = 0; j < 4; ++j) {
            int seg = tid + j * 256;
            int r = seg >> 3, s8 = seg & 7;
            cpasync16(sbase + SM_B + buf * SLAB + r * PITCH + s8 * 16,
                      g_O + (size_t)(bj * TILE + r) * DDIM + kc * KCH + s8 * 8);
        }
    };

    float acc[2][8][4];
    auto compute_chunk = [&](uint32_t baseA, uint32_t baseB) {
#pragma unroll
        for (int ks = 0; ks < 4; ++ks) {
            uint32_t a[2][4];
#pragma unroll
            for (int mt = 0; mt < 2; ++mt)
                ldm_x4(a[mt][0], a[mt][1], a[mt][2], a[mt][3],
                       baseA + aoff[mt] + ks * 32);
            uint32_t b[4][4];
#pragma unroll
            for (int nq = 0; nq < 4; ++nq)
                ldm_x4(b[nq][0], b[nq][1], b[nq][2], b[nq][3],
                       baseB + boff[nq] + ks * 32);
#pragma unroll
            for (int mt = 0; mt < 2; ++mt)
#pragma unroll
                for (int ntt = 0; ntt < 8; ++ntt)
                    mma16816(acc[mt][ntt], a[mt],
                             b[ntt >> 1][(ntt & 1) * 2],
                             b[ntt >> 1][(ntt & 1) * 2 + 1]);
        }
    };

    // load all of A (one commit group)
#pragma unroll
    for (int kc = 0; kc < NCH; ++kc) loadA(kc);
    cp_commit();

    const bool diag0 = (bj0 == bi);
    if (!diag0) {                      // prefetch first tile's chunks 0,1
        loadB(bj0, 0, 0); cp_commit();
        loadB(bj0, 1, 1); cp_commit();
    }

    for (int s = 0; s < nt; ++s) {
        const int bj = bj0 + s;
        const bool diag = (bj == bi);
        const int colBase = bj * TILE;

#pragma unroll
        for (int mt = 0; mt < 2; ++mt)
#pragma unroll
            for (int ntt = 0; ntt < 8; ++ntt)
#pragma unroll
                for (int k = 0; k < 4; ++k) acc[mt][ntt][k] = 0.f;

        if (diag) {                    // s == 0; B = A slabs, no loads needed
            bool pf = (nt > 1);
            if (pf) {                  // overlap next tile's first chunks
                loadB(bj0 + 1, 0, 0); cp_commit();
                loadB(bj0 + 1, 1, 1); cp_commit();
            }
            if (pf) cp_wait2(); else cp_wait0();   // A done (oldest group)
            __syncthreads();
#pragma unroll 2
            for (int kc = 0; kc < NCH; ++kc) {
                uint32_t baseA = sbase + SM_A + kc * SLAB;
                compute_chunk(baseA, baseA);
            }
        } else {
#pragma unroll 1
            for (int kc = 0; kc < NCH; ++kc) {
                if (kc < NCH - 1) cp_wait1(); else cp_wait0();
                __syncthreads();
                compute_chunk(sbase + SM_A + kc * SLAB,
                              sbase + SM_B + (kc & 1) * SLAB);
                __syncthreads();
                if (kc + 2 < NCH) { loadB(bj, kc + 2, kc & 1); cp_commit(); }
            }
            if (s + 1 < nt) {          // prefetch next tile during epilogue
                loadB(bj + 1, 0, 0); cp_commit();
                loadB(bj + 1, 1, 1); cp_commit();
            }
        }

        // ---- epilogue pass 1: exp, row sums, stage e to bf16 smem ----
        __syncthreads();               // previous tile's column pass done
        float sE[2][2]  = {{0.f, 0.f}, {0.f, 0.f}};
        float sE3[2][2] = {{0.f, 0.f}, {0.f, 0.f}};
#pragma unroll
        for (int mt = 0; mt < 2; ++mt)
#pragma unroll
            for (int ntt = 0; ntt < 8; ++ntt) {
                float e0 = __expf(acc[mt][ntt][0]);
                float e1 = __expf(acc[mt][ntt][1]);
                float e2 = __expf(acc[mt][ntt][2]);
                float e3 = __expf(acc[mt][ntt][3]);
                sE[mt][0]  += e0 + e1;
                sE[mt][1]  += e2 + e3;
                sE3[mt][0] += e0 * e0 * e0 + e1 * e1 * e1;
                sE3[mt][1] += e2 * e2 * e2 + e3 * e3 * e3;
                int c  = n_off + ntt * 8 + 2 * (lane & 3);
                int r0 = m_off + mt * 16 + (lane >> 2);
                int r1 = r0 + 8;
                *reinterpret_cast<__nv_bfloat162*>(
                    sTb + r0 * 128 + ((c + 2 * r0) & 127)) =
                    __floats2bfloat162_rn(e0, e1);
                *reinterpret_cast<__nv_bfloat162*>(
                    sTb + r1 * 128 + ((c + 2 * r1) & 127)) =
                    __floats2bfloat162_rn(e2, e3);
            }
#pragma unroll
        for (int mt = 0; mt < 2; ++mt)
#pragma unroll
            for (int h = 0; h < 2; ++h) {
                float vE = sE[mt][h], vB = sE3[mt][h];
                vE += __shfl_xor_sync(0xffffffffu, vE, 1);
                vE += __shfl_xor_sync(0xffffffffu, vE, 2);
                vB += __shfl_xor_sync(0xffffffffu, vB, 1);
                vB += __shfl_xor_sync(0xffffffffu, vB, 2);
                if ((lane & 3) == 0) {
                    int row = rowBase + m_off + mt * 16 + h * 8 + (lane >> 2);
                    atomicAdd(&g_sumE[row], vE);
                    atomicAdd(&g_sumE3[row], vB);
                }
            }
        __syncthreads();
        // ---- pass 2 (off-diag): column sums via transposed staged reads ----
        if (!diag && tid < 128) {
            float cE = 0.f, cE3 = 0.f;
#pragma unroll 8
            for (int r = 0; r < 128; ++r) {
                float e = __bfloat162float(sTb[r * 128 + ((tid + 2 * r) & 127)]);
                cE  += e;
                cE3 += e * e * e;
            }
            atomicAdd(&g_sumE[colBase + tid], cE);
            atomicAdd(&g_sumE3[colBase + tid], cE3);
        }
    }
}

// --------------------------------- kernel 3: partner dot + per-row loss term
__global__ __launch_bounds__(128) void finalize_kernel(float* __restrict__ out) {
    const int i = blockIdx.x;
    const int p = i ^ HALFN;
    const int tid = threadIdx.x;
    const __nv_bfloat162* a =
        reinterpret_cast<const __nv_bfloat162*>(g_O + (size_t)i * DDIM);
    const __nv_bfloat162* b =
        reinterpret_cast<const __nv_bfloat162*>(g_O + (size_t)p * DDIM);
    float d = 0.f;
#pragma unroll
    for (int j = tid; j < DDIM / 2; j += 128) {
        __nv_bfloat162 x = a[j], y = b[j];
        d += __bfloat162float(x.x) * __bfloat162float(y.x) +
             __bfloat162float(x.y) * __bfloat162float(y.y);
    }
#pragma unroll
    for (int o = 16; o; o >>= 1) d += __shfl_xor_sync(0xffffffffu, d, o);
    __shared__ float ws[4];
    if ((tid & 31) == 0) ws[tid >> 5] = d;
    __syncthreads();
    if (tid == 0) {
        d = ws[0] + ws[1] + ws[2] + ws[3];
        float ed  = __expf(d);            // exp(d_ip)
        float e3d = ed * ed * ed;         // exp(3 d_ip)
        float c   = ed * ed;              // pos cost = exp(2 d_ip)
        float Ap = g_sumE[i]  - 2.71828182845904523f - ed;   // minus self, partner
        float Bp = g_sumE3[i] - 20.0855369231876677f - e3d;
        float negmean = Bp / Ap;
        float denom = c + (float)(NROWS - 2) * negmean;
        float term = logf(denom) - 2.f * d;
        atomicAdd(out, term * (1.0f / (float)NROWS));
    }
}

// ------------------------------------------------------------------ launch
extern "C" void kernel_launch(void* const* d_in, const int* in_sizes, int n_in,
                              void* d_out, int out_size) {
    (void)in_sizes; (void)n_in; (void)out_size;
    // inputs: [0]=features (unused), [1]=out_1, [2]=out_2, [3]=indexes (arange)
    const float* out1 = (const float*)d_in[1];
    const float* out2 = (const float*)d_in[2];
    float* out = (float*)d_out;

    cudaFuncSetAttribute(gemm_exp_sym,
                         cudaFuncAttributeMaxDynamicSharedMemorySize, SM_SZ);

    cudaMemsetAsync(out, 0, sizeof(float), 0);
    normalize_kernel<<<NROWS, 128>>>(out1, out2);
    gemm_exp_sym<<<NGROUPS, 256, SM_SZ>>>();
    finalize_kernel<<<NROWS, 128>>>(out);
}

// round 5
// speedup vs baseline: 1.0684x; 1.0684x over previous
#include <cuda_runtime.h>
#include <cuda_bf16.h>
#include <cstdint>

// SupCon hard-contrastive loss via symmetric O*O^T (bf16 mma.sync):
//   nce = (1/2B) * sum_i [ log( exp(2 d_ip) + (2B-2)*B'_i/A'_i ) - 2 d_ip ]
// A'_i, B'_i = full-row sums of exp(d_ij), exp(3 d_ij) minus analytic
// self/partner terms. Triangular block tiles (2080): off-diagonal tiles
// contribute row sums AND (symmetry) column sums via bf16 smem transpose.
// Mainloop: 4-stage cp.async pipeline, ONE barrier per K-chunk.

#define NROWS 8192
#define HALFN 4096
#define DDIM  512
#define TILE  128
#define KC    32
#define NKC   (DDIM / KC)        // 16
#define PITCHB 80                // smem row pitch bytes (conflict-free ldmatrix)
#define NSTG  4
#define STGSZ 20480              // per stage: A(10240) + B(10240)
#define NTILES 2080              // 64*65/2

#define SM_SZ (NSTG * STGSZ)     // 81920 bytes (staging reuses stages 0-1)

__device__ __nv_bfloat16 g_O[(size_t)NROWS * DDIM];  // normalized rows, bf16
__device__ float g_sumE[NROWS];                      // sum_j exp(d_ij)
__device__ float g_sumE3[NROWS];                     // sum_j exp(3 d_ij)

// ---------------------------------------------------------------- helpers
__device__ __forceinline__ void cpasync16(uint32_t saddr, const void* gaddr) {
    asm volatile("cp.async.cg.shared.global [%0], [%1], 16;\n" ::
                 "r"(saddr), "l"(gaddr));
}
__device__ __forceinline__ void cp_commit() {
    asm volatile("cp.async.commit_group;\n");
}
__device__ __forceinline__ void ldm_x4(uint32_t& r0, uint32_t& r1, uint32_t& r2,
                                       uint32_t& r3, uint32_t addr) {
    asm volatile("ldmatrix.sync.aligned.m8n8.x4.shared.b16 {%0,%1,%2,%3}, [%4];\n"
                 : "=r"(r0), "=r"(r1), "=r"(r2), "=r"(r3) : "r"(addr));
}
__device__ __forceinline__ void mma16816(float* d, const uint32_t* a,
                                         uint32_t b0, uint32_t b1) {
    asm volatile(
        "mma.sync.aligned.m16n8k16.row.col.f32.bf16.bf16.f32 "
        "{%0,%1,%2,%3}, {%4,%5,%6,%7}, {%8,%9}, {%0,%1,%2,%3};\n"
        : "+f"(d[0]), "+f"(d[1]), "+f"(d[2]), "+f"(d[3])
        : "r"(a[0]), "r"(a[1]), "r"(a[2]), "r"(a[3]), "r"(b0), "r"(b1));
}

// ------------------- kernel 1: normalize -> bf16 (also zeroes accumulators)
__global__ __launch_bounds__(128) void normalize_kernel(const float* __restrict__ o1,
                                                        const float* __restrict__ o2,
                                                        float* __restrict__ out) {
    const int row = blockIdx.x;
    const int tid = threadIdx.x;
    if (row == 0 && tid == 0) *out = 0.f;
    const float* src = (row < HALFN) ? (o1 + (size_t)row * DDIM)
                                     : (o2 + (size_t)(row - HALFN) * DDIM);
    float4 v = reinterpret_cast<const float4*>(src)[tid];
    float ss = v.x * v.x + v.y * v.y + v.z * v.z + v.w * v.w;
#pragma unroll
    for (int o = 16; o; o >>= 1) ss += __shfl_xor_sync(0xffffffffu, ss, o);
    __shared__ float ws[4];
    if ((tid & 31) == 0) ws[tid >> 5] = ss;
    __syncthreads();
    float rn = rsqrtf(ws[0] + ws[1] + ws[2] + ws[3]);
    __nv_bfloat162* dst =
        reinterpret_cast<__nv_bfloat162*>(g_O + (size_t)row * DDIM) + tid * 2;
    dst[0] = __floats2bfloat162_rn(v.x * rn, v.y * rn);
    dst[1] = __floats2bfloat162_rn(v.z * rn, v.w * rn);
    if (tid == 0) { g_sumE[row] = 0.f; g_sumE3[row] = 0.f; }
}

// ---------------- kernel 2: triangular C = O*O^T tiles, fused exp + row/col sums
__global__ __launch_bounds__(256) void gemm_exp_sym() {
    extern __shared__ char smem[];
    const uint32_t sbase = (uint32_t)__cvta_generic_to_shared(smem);
    __nv_bfloat16* sTb = reinterpret_cast<__nv_bfloat16*>(smem);  // staging (reuse)
    const int tid  = threadIdx.x;
    const int lane = tid & 31;
    const int warp = tid >> 5;                  // 8 warps: 4 (M) x 2 (N)

    // decode triangular tile index: t = bj*(bj+1)/2 + bi, bi <= bj
    const int t = blockIdx.x;
    int bj = (int)((sqrtf(8.0f * (float)t + 1.0f) - 1.0f) * 0.5f);
    while ((bj + 1) * (bj + 2) / 2 <= t) ++bj;
    while (bj * (bj + 1) / 2 > t) --bj;
    const int bi = t - bj * (bj + 1) / 2;
    const bool diag = (bi == bj);
    const int rowBase = bi * TILE;
    const int colBase = bj * TILE;

    const int m_off = (warp >> 1) * 32;
    const int n_off = (warp & 1) * 64;

    // ldmatrix per-lane offsets (bytes within a stage half)
    const int rA   = ((lane >> 3) & 1) * 8 + (lane & 7);
    const int segA = lane >> 4;
    int aoff[2];
#pragma unroll
    for (int mt = 0; mt < 2; ++mt)
        aoff[mt] = (m_off + mt * 16 + rA) * PITCHB + segA * 16;

    const int rB   = (lane & 7) + ((lane >> 4) << 3);
    const int segB = (lane >> 3) & 1;
    int boff[4];
#pragma unroll
    for (int nq = 0; nq < 4; ++nq)
        boff[nq] = (n_off + nq * 16 + rB) * PITCHB + segB * 16;

    float acc[2][8][4];
#pragma unroll
    for (int mt = 0; mt < 2; ++mt)
#pragma unroll
        for (int nt = 0; nt < 8; ++nt)
#pragma unroll
            for (int k = 0; k < 4; ++k) acc[mt][nt][k] = 0.f;

    // chunk loader: 512 16B segs per matrix, 256 threads -> 2 each per matrix
    auto load_chunk = [&](int kc, int st) {
#pragma unroll
        for (int j = 0; j < 2; ++j) {
            int seg = tid + j * 256;
            int r = seg >> 2, s = seg & 3;
            cpasync16(sbase + st * STGSZ + r * PITCHB + s * 16,
                      g_O + (size_t)(rowBase + r) * DDIM + kc * KC + s * 8);
            cpasync16(sbase + st * STGSZ + 10240 + r * PITCHB + s * 16,
                      g_O + (size_t)(colBase + r) * DDIM + kc * KC + s * 8);
        }
    };

    // prologue: fill 3 stages
#pragma unroll
    for (int p = 0; p < 3; ++p) { load_chunk(p, p); cp_commit(); }

    for (int kc = 0; kc < NKC; ++kc) {
        // wait until chunk kc has arrived (per-warp), then barrier
        if (kc < NKC - 2)       asm volatile("cp.async.wait_group 2;\n" ::: "memory");
        else if (kc == NKC - 2) asm volatile("cp.async.wait_group 1;\n" ::: "memory");
        else                    asm volatile("cp.async.wait_group 0;\n" ::: "memory");
        __syncthreads();   // all warps' data in; stage (kc-1)&3 fully consumed

        if (kc + 3 < NKC) { load_chunk(kc + 3, (kc + 3) & 3); cp_commit(); }

        const uint32_t baseA = sbase + (kc & 3) * STGSZ;
        const uint32_t baseB = baseA + 10240;
#pragma unroll
        for (int ks = 0; ks < 2; ++ks) {
            uint32_t a[2][4];
#pragma unroll
            for (int mt = 0; mt < 2; ++mt)
                ldm_x4(a[mt][0], a[mt][1], a[mt][2], a[mt][3],
                       baseA + aoff[mt] + ks * 32);
            uint32_t b[4][4];
#pragma unroll
            for (int nq = 0; nq < 4; ++nq)
                ldm_x4(b[nq][0], b[nq][1], b[nq][2], b[nq][3],
                       baseB + boff[nq] + ks * 32);
#pragma unroll
            for (int mt = 0; mt < 2; ++mt)
#pragma unroll
                for (int nt = 0; nt < 8; ++nt)
                    mma16816(acc[mt][nt], a[mt],
                             b[nt >> 1][(nt & 1) * 2],
                             b[nt >> 1][(nt & 1) * 2 + 1]);
        }
    }

    // ---- epilogue pass 1: exp, row sums, stage e to bf16 smem ----
    __syncthreads();       // all warps done with operand smem (reused below)
    float sE[2][2]  = {{0.f, 0.f}, {0.f, 0.f}};
    float sE3[2][2] = {{0.f, 0.f}, {0.f, 0.f}};
#pragma unroll
    for (int mt = 0; mt < 2; ++mt)
#pragma unroll
        for (int nt = 0; nt < 8; ++nt) {
            float e0 = __expf(acc[mt][nt][0]);
            float e1 = __expf(acc[mt][nt][1]);
            float e2 = __expf(acc[mt][nt][2]);
            float e3 = __expf(acc[mt][nt][3]);
            sE[mt][0]  += e0 + e1;
            sE[mt][1]  += e2 + e3;
            sE3[mt][0] += e0 * e0 * e0 + e1 * e1 * e1;
            sE3[mt][1] += e2 * e2 * e2 + e3 * e3 * e3;
            int c  = n_off + nt * 8 + 2 * (lane & 3);
            int r0 = m_off + mt * 16 + (lane >> 2);
            int r1 = r0 + 8;
            *reinterpret_cast<__nv_bfloat162*>(
                sTb + r0 * 128 + ((c + 2 * r0) & 127)) =
                __floats2bfloat162_rn(e0, e1);
            *reinterpret_cast<__nv_bfloat162*>(
                sTb + r1 * 128 + ((c + 2 * r1) & 127)) =
                __floats2bfloat162_rn(e2, e3);
        }
#pragma unroll
    for (int mt = 0; mt < 2; ++mt)
#pragma unroll
        for (int h = 0; h < 2; ++h) {
            float vE = sE[mt][h], vB = sE3[mt][h];
            vE += __shfl_xor_sync(0xffffffffu, vE, 1);
            vE += __shfl_xor_sync(0xffffffffu, vE, 2);
            vB += __shfl_xor_sync(0xffffffffu, vB, 1);
            vB += __shfl_xor_sync(0xffffffffu, vB, 2);
            if ((lane & 3) == 0) {
                int row = rowBase + m_off + mt * 16 + h * 8 + (lane >> 2);
                atomicAdd(&g_sumE[row], vE);
                atomicAdd(&g_sumE3[row], vB);
            }
        }
    __syncthreads();
    // ---- pass 2 (off-diag): column sums via transposed staged reads ----
    if (!diag && tid < 128) {
        float cE = 0.f, cE3 = 0.f;
#pragma unroll 8
        for (int r = 0; r < 128; ++r) {
            float e = __bfloat162float(sTb[r * 128 + ((tid + 2 * r) & 127)]);
            cE  += e;
            cE3 += e * e * e;
        }
        atomicAdd(&g_sumE[colBase + tid], cE);
        atomicAdd(&g_sumE3[colBase + tid], cE3);
    }
}

// --------------------------------- kernel 3: partner dot + per-row loss term
__global__ __launch_bounds__(128) void finalize_kernel(float* __restrict__ out) {
    const int i = blockIdx.x;
    const int p = i ^ HALFN;
    const int tid = threadIdx.x;
    const __nv_bfloat162* a =
        reinterpret_cast<const __nv_bfloat162*>(g_O + (size_t)i * DDIM);
    const __nv_bfloat162* b =
        reinterpret_cast<const __nv_bfloat162*>(g_O + (size_t)p * DDIM);
    float d = 0.f;
#pragma unroll
    for (int j = tid; j < DDIM / 2; j += 128) {
        __nv_bfloat162 x = a[j], y = b[j];
        d += __bfloat162float(x.x) * __bfloat162float(y.x) +
             __bfloat162float(x.y) * __bfloat162float(y.y);
    }
#pragma unroll
    for (int o = 16; o; o >>= 1) d += __shfl_xor_sync(0xffffffffu, d, o);
    __shared__ float ws[4];
    if ((tid & 31) == 0) ws[tid >> 5] = d;
    __syncthreads();
    if (tid == 0) {
        d = ws[0] + ws[1] + ws[2] + ws[3];
        float ed  = __expf(d);            // exp(d_ip)
        float e3d = ed * ed * ed;         // exp(3 d_ip)
        float c   = ed * ed;              // pos cost = exp(2 d_ip)
        float Ap = g_sumE[i]  - 2.71828182845904523f - ed;   // minus self, partner
        float Bp = g_sumE3[i] - 20.0855369231876677f - e3d;
        float negmean = Bp / Ap;
        float denom = c + (float)(NROWS - 2) * negmean;
        float term = logf(denom) - 2.f * d;
        atomicAdd(out, term * (1.0f / (float)NROWS));
    }
}

// pad launch so ncu's "-s 5 -c 1" capture lands on the GEMM (launch index 5
// = 2nd call's gemm in the 4-launch sequence norm,gemm,fin,pad).
__global__ void profile_pad_kernel() {}

// ------------------------------------------------------------------ launch
extern "C" void kernel_launch(void* const* d_in, const int* in_sizes, int n_in,
                              void* d_out, int out_size) {
    (void)in_sizes; (void)n_in; (void)out_size;
    // inputs: [0]=features (unused), [1]=out_1, [2]=out_2, [3]=indexes (arange)
    const float* out1 = (const float*)d_in[1];
    const float* out2 = (const float*)d_in[2];
    float* out = (float*)d_out;

    cudaFuncSetAttribute(gemm_exp_sym,
                         cudaFuncAttributeMaxDynamicSharedMemorySize, SM_SZ);

    normalize_kernel<<<NROWS, 128>>>(out1, out2, out);
    gemm_exp_sym<<<NTILES, 256, SM_SZ>>>();
    finalize_kernel<<<NROWS, 128>>>(out);
    profile_pad_kernel<<<1, 32>>>();
}